// round 1
// baseline (speedup 1.0000x reference)
#include <cuda_runtime.h>
#include <cstdint>

// Problem constants (fixed by the reference): B=2, H=32, D=128, S_MAX=8192, S_NEW=512.
// BH and D are hardcoded; S_MAX / S_NEW derived from in_sizes for robustness.
#define BH 64
#define DHEAD 128
#define SMAX_MAX 8192

// Inverse scatter map: inv[s] = i if input_pos[i] == s else -1.
__device__ int g_inv[SMAX_MAX];

__global__ void reset_inv_kernel(int smax) {
    int i = blockIdx.x * blockDim.x + threadIdx.x;
    if (i < smax) g_inv[i] = -1;
}

__global__ void scatter_inv_kernel(const int* __restrict__ pos, int snew) {
    int i = blockIdx.x * blockDim.x + threadIdx.x;
    if (i < snew) {
        int p = pos[i];
        if (p >= 0 && p < SMAX_MAX) g_inv[p] = i;
    }
}

// out1 = k_cache with rows at input_pos replaced by k_val
// out2 = v_cache with rows at input_pos replaced by v_val
// One float4 per thread per output; each row of D=128 floats = 32 float4.
__global__ void copy_kv_kernel(const float4* __restrict__ k_cache,
                               const float4* __restrict__ v_cache,
                               const float4* __restrict__ k_val,
                               const float4* __restrict__ v_val,
                               float4* __restrict__ out1,
                               float4* __restrict__ out2,
                               int smax, int snew) {
    const int VPR = DHEAD / 4;  // 32 float4 per row
    size_t idx = (size_t)blockIdx.x * blockDim.x + threadIdx.x;
    size_t total = (size_t)BH * smax * VPR;
    if (idx >= total) return;

    int j = (int)(idx & (VPR - 1));
    size_t row = idx >> 5;               // (bh, s)
    int s = (int)(row % smax);
    size_t bh = row / smax;

    int i = g_inv[s];
    if (i >= 0) {
        size_t src = ((bh * (size_t)snew) + (size_t)i) * VPR + j;
        out1[idx] = k_val[src];
        out2[idx] = v_val[src];
    } else {
        out1[idx] = k_cache[idx];
        out2[idx] = v_cache[idx];
    }
}

// out0 = transpose of kt_cache: [BH, D, S_MAX] -> [BH, S_MAX, D]
// 32x32 shared-memory tile, padded column to avoid bank conflicts.
__global__ void transpose_kt_kernel(const float* __restrict__ kt_cache,
                                    float* __restrict__ out0,
                                    int smax) {
    __shared__ float tile[32][33];
    int bh = blockIdx.z;
    int s0 = blockIdx.x * 32;
    int d0 = blockIdx.y * 32;

    const float* src = kt_cache + (size_t)bh * DHEAD * smax;
    // Load: tile[r][tx] = kt[bh, d0+r, s0+tx]  (coalesced along s)
    #pragma unroll
    for (int r = threadIdx.y; r < 32; r += 8)
        tile[r][threadIdx.x] = src[(size_t)(d0 + r) * smax + (s0 + threadIdx.x)];
    __syncthreads();

    float* dst = out0 + (size_t)bh * smax * DHEAD;
    // Store: out0[bh, s0+r, d0+tx] = tile[tx][r]  (coalesced along d)
    #pragma unroll
    for (int r = threadIdx.y; r < 32; r += 8)
        dst[(size_t)(s0 + r) * DHEAD + (d0 + threadIdx.x)] = tile[threadIdx.x][r];
}

// Overwrite the scattered rows of out0 with k_val (after the transpose).
__global__ void scatter_out0_kernel(const int* __restrict__ pos,
                                    const float4* __restrict__ k_val,
                                    float4* __restrict__ out0,
                                    int smax, int snew) {
    const int VPR = DHEAD / 4;
    size_t idx = (size_t)blockIdx.x * blockDim.x + threadIdx.x;
    size_t total = (size_t)BH * snew * VPR;
    if (idx >= total) return;

    int j = (int)(idx & (VPR - 1));
    size_t row = idx >> 5;               // (bh, i)
    int i = (int)(row % snew);
    size_t bh = row / snew;
    int s = pos[i];

    out0[((bh * (size_t)smax) + (size_t)s) * VPR + j] = k_val[idx];
}

extern "C" void kernel_launch(void* const* d_in, const int* in_sizes, int n_in,
                              void* d_out, int out_size) {
    const int*   pos      = (const int*)d_in[0];
    const float* k_val    = (const float*)d_in[1];
    const float* v_val    = (const float*)d_in[2];
    const float* k_cache  = (const float*)d_in[3];
    const float* kt_cache = (const float*)d_in[4];
    const float* v_cache  = (const float*)d_in[5];

    int snew = in_sizes[0];
    int smax = in_sizes[3] / (BH * DHEAD);

    float* out  = (float*)d_out;
    size_t per  = (size_t)BH * smax * DHEAD;
    float* out0 = out;             // ktᵀ result
    float* out1 = out + per;       // k result
    float* out2 = out + 2 * per;   // v result

    // 1-2. Build inverse scatter map.
    reset_inv_kernel<<<(smax + 255) / 256, 256>>>(smax);
    scatter_inv_kernel<<<(snew + 255) / 256, 256>>>(pos, snew);

    // 3. Fused k/v copy-with-scatter (float4 vectorized).
    {
        size_t total = (size_t)BH * smax * (DHEAD / 4);
        int threads = 256;
        int blocks = (int)((total + threads - 1) / threads);
        copy_kv_kernel<<<blocks, threads>>>(
            (const float4*)k_cache, (const float4*)v_cache,
            (const float4*)k_val,   (const float4*)v_val,
            (float4*)out1, (float4*)out2, smax, snew);
    }

    // 4. Tiled transpose of kt_cache into out0.
    {
        dim3 tb(32, 8);
        dim3 tg(smax / 32, DHEAD / 32, BH);
        transpose_kt_kernel<<<tg, tb>>>(kt_cache, out0, smax);
    }

    // 5. Overwrite scattered rows of out0 with k_val.
    {
        size_t total = (size_t)BH * snew * (DHEAD / 4);
        int threads = 256;
        int blocks = (int)((total + threads - 1) / threads);
        scatter_out0_kernel<<<blocks, threads>>>(
            pos, (const float4*)k_val, (float4*)out0, smax, snew);
    }
}

// round 2
// speedup vs baseline: 1.2627x; 1.2627x over previous
#include <cuda_runtime.h>
#include <cstdint>

// Problem constants: B=2, H=32, D=128, S_MAX=8192, S_NEW=512 (fp32).
#define BH 64
#define DHEAD 128
#define SMAX_MAX 8192

// Inverse scatter map: inv[s] = i if input_pos[i] == s else -1.
__device__ int g_inv[SMAX_MAX];

__global__ void reset_inv_kernel(int smax) {
    int i = blockIdx.x * blockDim.x + threadIdx.x;
    if (i < smax) g_inv[i] = -1;
}

__global__ void scatter_inv_kernel(const int* __restrict__ pos, int snew) {
    int i = blockIdx.x * blockDim.x + threadIdx.x;
    if (i < snew) {
        int p = pos[i];
        if (p >= 0 && p < SMAX_MAX) g_inv[p] = i;
    }
}

// out1 = k_cache with rows at input_pos replaced by k_val
// out2 = v_cache with rows at input_pos replaced by v_val
// One float4 per thread per output; each row (D=128 floats) = 32 float4,
// so every warp owns exactly one (bh,s) row -> the scatter branch is warp-uniform.
__global__ void copy_kv_kernel(const float4* __restrict__ k_cache,
                               const float4* __restrict__ v_cache,
                               const float4* __restrict__ k_val,
                               const float4* __restrict__ v_val,
                               float4* __restrict__ out1,
                               float4* __restrict__ out2,
                               int smax, int snew) {
    const int VPR = DHEAD / 4;  // 32
    size_t idx = (size_t)blockIdx.x * blockDim.x + threadIdx.x;
    size_t total = (size_t)BH * smax * VPR;
    if (idx >= total) return;

    int j = (int)(idx & (VPR - 1));
    size_t row = idx >> 5;               // (bh, s)
    int s = (int)(row % smax);
    size_t bh = row / smax;

    int i = g_inv[s];
    if (i >= 0) {
        size_t src = ((bh * (size_t)snew) + (size_t)i) * VPR + j;
        out1[idx] = k_val[src];
        out2[idx] = v_val[src];
    } else {
        out1[idx] = k_cache[idx];
        out2[idx] = v_cache[idx];
    }
}

// out0 = transpose of kt_cache [BH, D, S_MAX] -> [BH, S_MAX, D],
// with rows at input_pos replaced by k_val (fused scatter epilogue).
//
// Tile: 32 s-values x 128 d-values per block (full D). float4 on both global
// sides. Shared tile stored [s][d] with 4-float pad (pitch 132) so the read
// side can use aligned LDS.128.
__global__ void transpose_kt_fused_kernel(const float4* __restrict__ kt,   // [BH, D, S_MAX/4]
                                          const float4* __restrict__ k_val,// [BH, S_NEW, 32]
                                          float4* __restrict__ out0,       // [BH, S_MAX, 32]
                                          int smax, int snew) {
    __shared__ float tile[32][132];   // [s][d], pad keeps 16B alignment (132*4=528=33*16)

    const int bh = blockIdx.y;
    const int s0 = blockIdx.x * 32;
    const int t  = threadIdx.x;       // 256 threads

    // ---- load phase: float4 along s ----
    // lane mapping: s4 = t & 7 (float4 index within 32 s), d = (t>>3) + 32*it
    const int s4   = t & 7;
    const int d_lo = t >> 3;          // 0..31
    const size_t srow4 = (size_t)smax >> 2;
    const float4* src = kt + (size_t)bh * DHEAD * srow4;

    #pragma unroll
    for (int it = 0; it < 4; ++it) {
        int d = d_lo + it * 32;
        float4 v = src[(size_t)d * srow4 + (size_t)(s0 >> 2) + s4];
        tile[s4 * 4 + 0][d] = v.x;
        tile[s4 * 4 + 1][d] = v.y;
        tile[s4 * 4 + 2][d] = v.z;
        tile[s4 * 4 + 3][d] = v.w;
    }
    __syncthreads();

    // ---- store phase: float4 along d, one warp per output row ----
    const int l = t & 31;             // float4 column 0..31
    const int w = t >> 5;             // warp 0..7
    float4* dst = out0 + (size_t)bh * smax * (DHEAD / 4);

    #pragma unroll
    for (int it = 0; it < 4; ++it) {
        int s  = w + it * 8;          // 0..31
        int gs = s0 + s;
        int i  = g_inv[gs];           // warp-uniform
        float4 v;
        if (i >= 0) {
            v = k_val[((size_t)bh * snew + (size_t)i) * 32 + l];
        } else {
            v = *(const float4*)&tile[s][l * 4];
        }
        dst[(size_t)gs * 32 + l] = v;
    }
}

extern "C" void kernel_launch(void* const* d_in, const int* in_sizes, int n_in,
                              void* d_out, int out_size) {
    const int*   pos      = (const int*)d_in[0];
    const float* k_val    = (const float*)d_in[1];
    const float* v_val    = (const float*)d_in[2];
    const float* k_cache  = (const float*)d_in[3];
    const float* kt_cache = (const float*)d_in[4];
    const float* v_cache  = (const float*)d_in[5];

    int snew = in_sizes[0];
    int smax = in_sizes[3] / (BH * DHEAD);

    float* out  = (float*)d_out;
    size_t per  = (size_t)BH * smax * DHEAD;
    float* out0 = out;             // ktᵀ result
    float* out1 = out + per;       // k result
    float* out2 = out + 2 * per;   // v result

    // 1-2. Build inverse scatter map.
    reset_inv_kernel<<<(smax + 255) / 256, 256>>>(smax);
    scatter_inv_kernel<<<(snew + 255) / 256, 256>>>(pos, snew);

    // 3. Fused k/v copy-with-scatter (float4 vectorized).
    {
        size_t total = (size_t)BH * smax * (DHEAD / 4);
        int threads = 256;
        int blocks = (int)((total + threads - 1) / threads);
        copy_kv_kernel<<<blocks, threads>>>(
            (const float4*)k_cache, (const float4*)v_cache,
            (const float4*)k_val,   (const float4*)v_val,
            (float4*)out1, (float4*)out2, smax, snew);
    }

    // 4. Vectorized transpose of kt_cache into out0 with fused scatter.
    {
        dim3 tg(smax / 32, BH);
        transpose_kt_fused_kernel<<<tg, 256>>>(
            (const float4*)kt_cache, (const float4*)k_val,
            (float4*)out0, smax, snew);
    }
}